// round 12
// baseline (speedup 1.0000x reference)
#include <cuda_runtime.h>
#include <cuda_bf16.h>

#define H_OUT 228
#define W_OUT 304
#define S_RAS 304
#define N_V   8192
#define M_F   2048
#define NSEG  4
#define MSEG  (M_F / NSEG)        // 512 faces per segment, one smem pass
#define TILE_W 32
#define TILE_H 8
#define TILES_X 10                // ceil(304/32)
#define TILES_Y 29                // ceil(228/8)
#define NTHR   256                // 1 px per thread
#define NPIX  (H_OUT * W_OUT)     // 69312 (divisible by 4)
#define FAR_V 100.0f
#define EPS_V 1e-7f
#define CULL_EPS 1e-4f

// scratch (no allocations allowed)
__device__ float4 g_s0[M_F];              // (A0, B0, C0, A1)
__device__ float4 g_s1[M_F];              // (B1, C1, A2, B2)
__device__ float4 g_s2[M_F];              // (C2, Az, Bz, Cz)
__device__ float4 g_bb[M_F];              // (xmin, xmax, ymin, ymax); NaN if degenerate
__device__ float  g_pm[NSEG * NPIX];      // per-segment max inv_z (every slot written)

__device__ __forceinline__ void pdl_wait() {
    asm volatile("griddepcontrol.wait;" ::: "memory");
}

// ---------------------------------------------------------------------------
// 1) fused vertex transform + face setup (one thread per face)
//    w0 = A0*px + B0*py + C0   (likewise w1, w2, iz) — affine in screen ndc
// ---------------------------------------------------------------------------
__global__ void __launch_bounds__(64) prep_kernel(const float* __restrict__ verts,
                                                  const int*   __restrict__ faces,
                                                  const float* __restrict__ Km,
                                                  const float* __restrict__ Rm,
                                                  const float* __restrict__ tm)
{
    int f = blockIdx.x * blockDim.x + threadIdx.x;
    if (f >= M_F) return;

    int i0 = faces[3 * f + 0];
    int i1 = faces[3 * f + 1];
    int i2 = faces[3 * f + 2];
    float vu[3], vv_[3], vd[3];
    {
        const int idxs[3] = {i0, i1, i2};
        #pragma unroll
        for (int v = 0; v < 3; v++) {
            vu[v]  = __ldg(&verts[3 * idxs[v] + 0]);
            vv_[v] = __ldg(&verts[3 * idxs[v] + 1]);
            vd[v]  = __ldg(&verts[3 * idxs[v] + 2]);
        }
    }

    float k0 = Km[0], k1 = Km[1], k2 = Km[2];
    float k3 = Km[3], k4 = Km[4], k5 = Km[5];
    float k6 = Km[6], k7 = Km[7], k8 = Km[8];

    // adjugate inverse of K
    float c00 = k4 * k8 - k5 * k7;
    float c01 = k5 * k6 - k3 * k8;
    float c02 = k3 * k7 - k4 * k6;
    float det = k0 * c00 + k1 * c01 + k2 * c02;
    float id  = __fdividef(1.0f, det);
    float i00 = c00 * id, i01 = (k2 * k7 - k1 * k8) * id, i02 = (k1 * k5 - k2 * k4) * id;
    float i10 = c01 * id, i11 = (k0 * k8 - k2 * k6) * id, i12 = (k2 * k3 - k0 * k5) * id;
    float i20 = c02 * id, i21 = (k1 * k6 - k0 * k7) * id, i22 = (k0 * k4 - k1 * k3) * id;

    float R0 = Rm[0], R1 = Rm[1], R2 = Rm[2];
    float R3 = Rm[3], R4 = Rm[4], R5 = Rm[5];
    float R6 = Rm[6], R7 = Rm[7], R8 = Rm[8];
    float t0_ = tm[0], t1_ = tm[1], t2_ = tm[2];

    float X[3], Y[3], Z[3];
    #pragma unroll
    for (int v = 0; v < 3; v++) {
        float p0 = vu[v]  * (float)W_OUT;
        float p1 = vv_[v] * (float)H_OUT;
        float d  = vd[v];

        float cx = (i00 * p0 + i01 * p1 + i02) * d;
        float cy = (i10 * p0 + i11 * p1 + i12) * d;
        float cz = (i20 * p0 + i21 * p1 + i22) * d;

        float qx = R0 * cx + R1 * cy + R2 * cz + t0_;
        float qy = R3 * cx + R4 * cy + R5 * cz + t1_;
        float qz = R6 * cx + R7 * cy + R8 * cz + t2_;

        float izd = __fdividef(1.0f, qz + EPS_V);
        float ppx = qx * izd;
        float ppy = qy * izd;

        float s0 = k0 * ppx + k1 * ppy + k2;
        float s1 = k3 * ppx + k4 * ppy + k5;

        float u2 = fminf(fmaxf(s0 * (1.0f / (float)W_OUT), 0.0f), 1.0f);
        float v2 = fminf(fmaxf(s1 * (1.0f / (float)H_OUT), 0.0f), 1.0f);

        X[v] = (u2 * (float)W_OUT) / (float)S_RAS * 2.0f - 1.0f;
        Y[v] = (v2 * (float)H_OUT) / (float)S_RAS * 2.0f - 1.0f;
        Z[v] = qz;
    }

    float y12 = Y[1] - Y[2];
    float x21 = X[2] - X[1];
    float y20 = Y[2] - Y[0];
    float x02 = X[0] - X[2];

    float denom = y12 * (X[0] - X[2]) + x21 * (Y[0] - Y[2]);
    bool  ok    = fabsf(denom) > 1e-10f;
    float inv   = __fdividef(1.0f, ok ? denom : 1.0f);

    float A0 = y12 * inv, B0 = x21 * inv;
    float A1 = y20 * inv, B1 = x02 * inv;
    float C0 = -(A0 * X[2] + B0 * Y[2]);
    float C1 = -(A1 * X[2] + B1 * Y[2]);
    float A2 = -(A0 + A1), B2 = -(B0 + B1), C2 = 1.0f - C0 - C1;

    float r0 = __fdividef(1.0f, Z[0]);
    float r1 = __fdividef(1.0f, Z[1]);
    float r2 = __fdividef(1.0f, Z[2]);
    float dr0 = r0 - r2, dr1 = r1 - r2;
    float Az = A0 * dr0 + A1 * dr1;
    float Bz = B0 * dr0 + B1 * dr1;
    float Cz = C0 * dr0 + C1 * dr1 + r2;

    g_s0[f] = make_float4(A0, B0, C0, A1);
    g_s1[f] = make_float4(B1, C1, A2, B2);
    g_s2[f] = make_float4(C2, Az, Bz, Cz);

    float xmn = fminf(X[0], fminf(X[1], X[2]));
    float xmx = fmaxf(X[0], fmaxf(X[1], X[2]));
    float ymn = fminf(Y[0], fminf(Y[1], Y[2]));
    float ymx = fmaxf(Y[0], fmaxf(Y[1], Y[2]));
    float nanv = __int_as_float(0x7fc00000);
    g_bb[f] = ok ? make_float4(xmn, xmx, ymn, ymx)
                 : make_float4(nanv, nanv, nanv, nanv);
}

// ---------------------------------------------------------------------------
// 2) tiled raster: block = (tileX, tileY, face-segment). 32x8-px tile,
//    256 threads (1 px/thread), 512 faces/segment in ONE smem pass.
//    Cull (bbox + conservative affine bounds) -> compact -> branchless sweep.
// ---------------------------------------------------------------------------
__global__ void __launch_bounds__(NTHR) raster_kernel()
{
    __shared__ float4 sA[MSEG];
    __shared__ float4 sB[MSEG];
    __shared__ float4 sC[MSEG];
    __shared__ int    s_cnt;

    const int tX = blockIdx.x, tY = blockIdx.y, seg = blockIdx.z;
    const int t  = threadIdx.x;
    if (t == 0) s_cnt = 0;

    // tile pixel-center bounds in ndc (py decreases with row index)
    const int c0t = tX * TILE_W, r0t = tY * TILE_H;
    const float x_lo = (2.0f * c0t + 1.0f - S_RAS) / (float)S_RAS;
    const float x_hi = (2.0f * (c0t + TILE_W - 1) + 1.0f - S_RAS) / (float)S_RAS;
    const float y_hi = (float)(S_RAS - 1 - 2 * r0t) / (float)S_RAS;
    const float y_lo = (float)(S_RAS - 1 - 2 * (r0t + TILE_H - 1)) / (float)S_RAS;
    const float ctx = 0.5f * (x_lo + x_hi), cty = 0.5f * (y_lo + y_hi);
    const float hx  = 0.5f * (x_hi - x_lo), hy  = 0.5f * (y_hi - y_lo);

    // this thread's pixel
    const int r = r0t + (t >> 5);
    const int c = c0t + (t & 31);
    const float py = (float)(S_RAS - 1 - 2 * r) / (float)S_RAS;
    const float px = (2.0f * c + 1.0f - S_RAS) / (float)S_RAS;

    __syncthreads();               // s_cnt visible
    pdl_wait();                    // prep's writes visible (no-op w/o PDL)

    // cull + compact: 512 faces, 2 per thread
    #pragma unroll
    for (int k = 0; k < MSEG / NTHR; k++) {
        int f = seg * MSEG + k * NTHR + t;
        float4 bb = g_bb[f];
        bool ov = (bb.x <= x_hi + CULL_EPS) && (bb.y >= x_lo - CULL_EPS) &&
                  (bb.z <= y_hi + CULL_EPS) && (bb.w >= y_lo - CULL_EPS);
        if (ov) {
            float4 s0 = g_s0[f];
            float4 s1 = g_s1[f];
            float4 s2 = g_s2[f];
            float b0m = s0.x * ctx + s0.y * cty + s0.z + fabsf(s0.x) * hx + fabsf(s0.y) * hy;
            float b1m = s0.w * ctx + s1.x * cty + s1.y + fabsf(s0.w) * hx + fabsf(s1.x) * hy;
            float b2m = s1.z * ctx + s1.w * cty + s2.x + fabsf(s1.z) * hx + fabsf(s1.w) * hy;
            if (b0m >= -CULL_EPS && b1m >= -CULL_EPS && b2m >= -CULL_EPS) {
                int slot = atomicAdd(&s_cnt, 1);
                sA[slot] = s0;
                sB[slot] = s1;
                sC[slot] = s2;
            }
        }
    }
    __syncthreads();
    const int cnt = s_cnt;

    float m = 0.0f;                // max inv_z (all inside faces have iz > 0)

    #pragma unroll 4
    for (int i = 0; i < cnt; i++) {
        float4 s0 = sA[i];
        float4 s1 = sB[i];
        float4 s2 = sC[i];
        float w0 = fmaf(s0.x, px, fmaf(s0.y, py, s0.z));
        float w1 = fmaf(s0.w, px, fmaf(s1.x, py, s1.y));
        float w2 = fmaf(s1.z, px, fmaf(s1.w, py, s2.x));
        float iz = fmaf(s2.y, px, fmaf(s2.z, py, s2.w));
        float mn = fminf(fminf(w0, w1), w2);
        m = fmaxf(m, (mn >= 0.0f) ? iz : 0.0f);   // branchless
    }

    if (r < H_OUT && c < W_OUT)
        g_pm[seg * NPIX + r * W_OUT + c] = m;
}

// ---------------------------------------------------------------------------
// 3) merge segments, write depth + sil (vectorized)
// ---------------------------------------------------------------------------
__global__ void finalize_kernel(float* __restrict__ out)
{
    int q = blockIdx.x * blockDim.x + threadIdx.x;    // quad index
    if (q >= NPIX / 4) return;
    pdl_wait();
    float4 a = *reinterpret_cast<const float4*>(&g_pm[4 * q]);
    float mv[4] = { a.x, a.y, a.z, a.w };
    #pragma unroll
    for (int s = 1; s < NSEG; s++) {
        float4 b = *reinterpret_cast<const float4*>(&g_pm[s * NPIX + 4 * q]);
        mv[0] = fmaxf(mv[0], b.x); mv[1] = fmaxf(mv[1], b.y);
        mv[2] = fmaxf(mv[2], b.z); mv[3] = fmaxf(mv[3], b.w);
    }
    float4 dep, sil;
    float* dp = &dep.x; float* sp = &sil.x;
    #pragma unroll
    for (int j = 0; j < 4; j++) {
        bool hit = mv[j] > 0.0f;
        dp[j] = hit ? fminf(FAR_V, 1.0f / mv[j]) : FAR_V;
        sp[j] = hit ? 1.0f : 0.0f;
    }
    *reinterpret_cast<float4*>(&out[4 * q])        = dep;
    *reinterpret_cast<float4*>(&out[NPIX + 4 * q]) = sil;
}

// ---------------------------------------------------------------------------
extern "C" void kernel_launch(void* const* d_in, const int* in_sizes, int n_in,
                              void* d_out, int out_size)
{
    const float* verts = (const float*)d_in[0];   // [1,8192,3] f32
    const int*   faces = (const int*)  d_in[1];   // [1,2048,3] i32
    const float* Km    = (const float*)d_in[2];   // [1,3,3]
    const float* Rm    = (const float*)d_in[3];   // [1,3,3]
    const float* tm    = (const float*)d_in[4];   // [1,3,1]
    float* out = (float*)d_out;

    prep_kernel<<<M_F / 64, 64>>>(verts, faces, Km, Rm, tm);

    // raster with PDL (overlap launch with prep tail)
    {
        cudaLaunchAttribute attr[1];
        attr[0].id = cudaLaunchAttributeProgrammaticStreamSerialization;
        attr[0].val.programmaticStreamSerializationAllowed = 1;
        cudaLaunchConfig_t cfg = {};
        cfg.gridDim  = dim3(TILES_X, TILES_Y, NSEG);   // 10 x 29 x 4 = 1160
        cfg.blockDim = dim3(NTHR, 1, 1);
        cfg.attrs = attr;
        cfg.numAttrs = 1;
        cudaLaunchKernelEx(&cfg, raster_kernel);
    }

    // finalize with PDL
    {
        cudaLaunchAttribute attr[1];
        attr[0].id = cudaLaunchAttributeProgrammaticStreamSerialization;
        attr[0].val.programmaticStreamSerializationAllowed = 1;
        cudaLaunchConfig_t cfg = {};
        cfg.gridDim  = dim3((NPIX / 4 + 127) / 128, 1, 1);
        cfg.blockDim = dim3(128, 1, 1);
        cfg.attrs = attr;
        cfg.numAttrs = 1;
        cudaLaunchKernelEx(&cfg, finalize_kernel, out);
    }
}

// round 13
// speedup vs baseline: 1.0537x; 1.0537x over previous
#include <cuda_runtime.h>
#include <cuda_bf16.h>

#define H_OUT 228
#define W_OUT 304
#define S_RAS 304
#define N_V   8192
#define M_F   2048
#define NSEG  2
#define MSEG  (M_F / NSEG)        // 1024 faces per segment, one smem pass
#define TILE_W 32
#define TILE_H 8
#define TILES_X 10                // ceil(304/32)
#define TILES_Y 29                // ceil(228/8)
#define NTHR   256                // 1 px per thread
#define NPIX  (H_OUT * W_OUT)     // 69312 (divisible by 4)
#define FAR_V 100.0f
#define EPS_V 1e-7f
#define CULL_EPS 1e-4f

// scratch (no allocations allowed)
__device__ float4 g_vt[N_V];              // per-vertex (X, Y, 1/z, unused)
__device__ float4 g_e0[M_F];              // (A0, B0, C0, A1)
__device__ float4 g_e1[M_F];              // (B1, C1, Az, Bz)
__device__ float  g_e2[M_F];              // Cz
__device__ float4 g_bb[M_F];              // (xmin, xmax, ymin, ymax); NaN if degenerate
__device__ float  g_pm[NSEG * NPIX];      // per-segment max inv_z (every slot written)

__device__ __forceinline__ void pdl_wait() {
    asm volatile("griddepcontrol.wait;" ::: "memory");
}

static void launch_pdl(void* fn, dim3 grid, dim3 block, void** args) {
    cudaLaunchAttribute attr[1];
    attr[0].id = cudaLaunchAttributeProgrammaticStreamSerialization;
    attr[0].val.programmaticStreamSerializationAllowed = 1;
    cudaLaunchConfig_t cfg = {};
    cfg.gridDim = grid; cfg.blockDim = block;
    cfg.attrs = attr; cfg.numAttrs = 1;
    cudaLaunchKernelExC(&cfg, fn, args);
}

// ---------------------------------------------------------------------------
// 1a) per-vertex transform: coalesced loads, short chain
// ---------------------------------------------------------------------------
__global__ void __launch_bounds__(128) vert_kernel(const float* __restrict__ verts,
                                                   const float* __restrict__ Km,
                                                   const float* __restrict__ Rm,
                                                   const float* __restrict__ tm)
{
    int i = blockIdx.x * blockDim.x + threadIdx.x;
    if (i >= N_V) return;

    float u  = verts[3 * i + 0];
    float vv = verts[3 * i + 1];
    float d  = verts[3 * i + 2];

    float k0 = Km[0], k1 = Km[1], k2 = Km[2];
    float k3 = Km[3], k4 = Km[4], k5 = Km[5];
    float k6 = Km[6], k7 = Km[7], k8 = Km[8];

    // adjugate inverse of K
    float c00 = k4 * k8 - k5 * k7;
    float c01 = k5 * k6 - k3 * k8;
    float c02 = k3 * k7 - k4 * k6;
    float det = k0 * c00 + k1 * c01 + k2 * c02;
    float id  = __fdividef(1.0f, det);
    float i00 = c00 * id, i01 = (k2 * k7 - k1 * k8) * id, i02 = (k1 * k5 - k2 * k4) * id;
    float i10 = c01 * id, i11 = (k0 * k8 - k2 * k6) * id, i12 = (k2 * k3 - k0 * k5) * id;
    float i20 = c02 * id, i21 = (k1 * k6 - k0 * k7) * id, i22 = (k0 * k4 - k1 * k3) * id;

    float p0 = u  * (float)W_OUT;
    float p1 = vv * (float)H_OUT;

    float cx = (i00 * p0 + i01 * p1 + i02) * d;
    float cy = (i10 * p0 + i11 * p1 + i12) * d;
    float cz = (i20 * p0 + i21 * p1 + i22) * d;

    float qx = Rm[0] * cx + Rm[1] * cy + Rm[2] * cz + tm[0];
    float qy = Rm[3] * cx + Rm[4] * cy + Rm[5] * cz + tm[1];
    float qz = Rm[6] * cx + Rm[7] * cy + Rm[8] * cz + tm[2];

    float izd = __fdividef(1.0f, qz + EPS_V);
    float ppx = qx * izd;
    float ppy = qy * izd;

    float s0 = k0 * ppx + k1 * ppy + k2;
    float s1 = k3 * ppx + k4 * ppy + k5;

    float u2 = fminf(fmaxf(s0 * (1.0f / (float)W_OUT), 0.0f), 1.0f);
    float v2 = fminf(fmaxf(s1 * (1.0f / (float)H_OUT), 0.0f), 1.0f);

    float X = (u2 * (float)W_OUT) / (float)S_RAS * 2.0f - 1.0f;
    float Y = (v2 * (float)H_OUT) / (float)S_RAS * 2.0f - 1.0f;
    float rz = __fdividef(1.0f, qz);

    g_vt[i] = make_float4(X, Y, rz, 0.0f);
}

// ---------------------------------------------------------------------------
// 1b) per-face edge setup (gathers from L2-resident g_vt)
//     w0 = A0*px + B0*py + C0 ; w1 likewise ; iz = Az*px + Bz*py + Cz
// ---------------------------------------------------------------------------
__global__ void __launch_bounds__(128) face_kernel(const int* __restrict__ faces)
{
    int f = blockIdx.x * blockDim.x + threadIdx.x;
    if (f >= M_F) return;

    int i0 = faces[3 * f + 0];
    int i1 = faces[3 * f + 1];
    int i2 = faces[3 * f + 2];
    pdl_wait();                 // g_vt ready (no-op once predecessor done)

    float4 v0 = g_vt[i0];
    float4 v1 = g_vt[i1];
    float4 v2 = g_vt[i2];

    float y12 = v1.y - v2.y;
    float x21 = v2.x - v1.x;
    float y20 = v2.y - v0.y;
    float x02 = v0.x - v2.x;

    float denom = y12 * (v0.x - v2.x) + x21 * (v0.y - v2.y);
    bool  ok    = fabsf(denom) > 1e-10f;
    float inv   = __fdividef(1.0f, ok ? denom : 1.0f);

    float A0 = y12 * inv, B0 = x21 * inv;
    float A1 = y20 * inv, B1 = x02 * inv;
    float C0 = -(A0 * v2.x + B0 * v2.y);
    float C1 = -(A1 * v2.x + B1 * v2.y);

    float dr0 = v0.z - v2.z, dr1 = v1.z - v2.z;
    float Az = A0 * dr0 + A1 * dr1;
    float Bz = B0 * dr0 + B1 * dr1;
    float Cz = C0 * dr0 + C1 * dr1 + v2.z;

    g_e0[f] = make_float4(A0, B0, C0, A1);
    g_e1[f] = make_float4(B1, C1, Az, Bz);
    g_e2[f] = Cz;

    float xmn = fminf(v0.x, fminf(v1.x, v2.x));
    float xmx = fmaxf(v0.x, fmaxf(v1.x, v2.x));
    float ymn = fminf(v0.y, fminf(v1.y, v2.y));
    float ymx = fmaxf(v0.y, fmaxf(v1.y, v2.y));
    float nanv = __int_as_float(0x7fc00000);
    g_bb[f] = ok ? make_float4(xmn, xmx, ymn, ymx)
                 : make_float4(nanv, nanv, nanv, nanv);
}

// ---------------------------------------------------------------------------
// 2) tiled raster: block = (tileX, tileY, face-segment). 32x8-px tile,
//    256 threads (1 px/thread), 1024 faces/segment in ONE smem pass.
//    Cull (bbox + conservative affine bounds) -> compact -> branchless sweep.
//    36B/face in smem (36KB total) keeps NSEG=2 within static smem.
// ---------------------------------------------------------------------------
__global__ void __launch_bounds__(NTHR) raster_kernel()
{
    __shared__ float4 sA[MSEG];
    __shared__ float4 sB[MSEG];
    __shared__ float  sC[MSEG];
    __shared__ int    s_cnt;

    const int tX = blockIdx.x, tY = blockIdx.y, seg = blockIdx.z;
    const int t  = threadIdx.x;
    if (t == 0) s_cnt = 0;

    // tile pixel-center bounds in ndc (py decreases with row index)
    const int c0t = tX * TILE_W, r0t = tY * TILE_H;
    const float x_lo = (2.0f * c0t + 1.0f - S_RAS) / (float)S_RAS;
    const float x_hi = (2.0f * (c0t + TILE_W - 1) + 1.0f - S_RAS) / (float)S_RAS;
    const float y_hi = (float)(S_RAS - 1 - 2 * r0t) / (float)S_RAS;
    const float y_lo = (float)(S_RAS - 1 - 2 * (r0t + TILE_H - 1)) / (float)S_RAS;
    const float ctx = 0.5f * (x_lo + x_hi), cty = 0.5f * (y_lo + y_hi);
    const float hx  = 0.5f * (x_hi - x_lo), hy  = 0.5f * (y_hi - y_lo);

    // this thread's pixel
    const int r = r0t + (t >> 5);
    const int c = c0t + (t & 31);
    const float py = (float)(S_RAS - 1 - 2 * r) / (float)S_RAS;
    const float px = (2.0f * c + 1.0f - S_RAS) / (float)S_RAS;

    __syncthreads();               // s_cnt visible
    pdl_wait();                    // face data ready

    // cull + compact: 1024 faces, 4 per thread
    #pragma unroll
    for (int k = 0; k < MSEG / NTHR; k++) {
        int f = seg * MSEG + k * NTHR + t;
        float4 bb = g_bb[f];
        bool ov = (bb.x <= x_hi + CULL_EPS) && (bb.y >= x_lo - CULL_EPS) &&
                  (bb.z <= y_hi + CULL_EPS) && (bb.w >= y_lo - CULL_EPS);
        if (ov) {
            float4 e0 = g_e0[f];
            float4 e1 = g_e1[f];
            float  Cz = g_e2[f];
            // conservative max of each barycentric over the tile rect
            float w0c = e0.x * ctx + e0.y * cty + e0.z;
            float w1c = e0.w * ctx + e1.x * cty + e1.y;
            float b0m = w0c + fabsf(e0.x) * hx + fabsf(e0.y) * hy;
            float b1m = w1c + fabsf(e0.w) * hx + fabsf(e1.x) * hy;
            float sa  = e0.x + e0.w, sb = e0.y + e1.x;
            float b2m = 1.0f - (w0c + w1c) + fabsf(sa) * hx + fabsf(sb) * hy;
            if (b0m >= -CULL_EPS && b1m >= -CULL_EPS && b2m >= -CULL_EPS) {
                int slot = atomicAdd(&s_cnt, 1);
                sA[slot] = e0;
                sB[slot] = e1;
                sC[slot] = Cz;
            }
        }
    }
    __syncthreads();
    const int cnt = s_cnt;

    float m = 0.0f;                // max inv_z (all inside faces have iz > 0)

    #pragma unroll 4
    for (int i = 0; i < cnt; i++) {
        float4 e0 = sA[i];
        float4 e1 = sB[i];
        float  Cz = sC[i];
        float w0 = fmaf(e0.x, px, fmaf(e0.y, py, e0.z));
        float w1 = fmaf(e0.w, px, fmaf(e1.x, py, e1.y));
        float iz = fmaf(e1.z, px, fmaf(e1.w, py, Cz));
        float ws = w0 + w1;
        float mn = fminf(fminf(w0, w1), 1.0f - ws);
        m = fmaxf(m, (mn >= 0.0f) ? iz : 0.0f);   // branchless
    }

    if (r < H_OUT && c < W_OUT)
        g_pm[seg * NPIX + r * W_OUT + c] = m;
}

// ---------------------------------------------------------------------------
// 3) merge segments, write depth + sil (vectorized)
// ---------------------------------------------------------------------------
__global__ void finalize_kernel(float* __restrict__ out)
{
    int q = blockIdx.x * blockDim.x + threadIdx.x;    // quad index
    if (q >= NPIX / 4) return;
    pdl_wait();
    float4 a = *reinterpret_cast<const float4*>(&g_pm[4 * q]);
    float4 b = *reinterpret_cast<const float4*>(&g_pm[NPIX + 4 * q]);
    float mv[4] = { fmaxf(a.x, b.x), fmaxf(a.y, b.y),
                    fmaxf(a.z, b.z), fmaxf(a.w, b.w) };
    float4 dep, sil;
    float* dp = &dep.x; float* sp = &sil.x;
    #pragma unroll
    for (int j = 0; j < 4; j++) {
        bool hit = mv[j] > 0.0f;
        dp[j] = hit ? fminf(FAR_V, 1.0f / mv[j]) : FAR_V;
        sp[j] = hit ? 1.0f : 0.0f;
    }
    *reinterpret_cast<float4*>(&out[4 * q])        = dep;
    *reinterpret_cast<float4*>(&out[NPIX + 4 * q]) = sil;
}

// ---------------------------------------------------------------------------
extern "C" void kernel_launch(void* const* d_in, const int* in_sizes, int n_in,
                              void* d_out, int out_size)
{
    const float* verts = (const float*)d_in[0];   // [1,8192,3] f32
    const int*   faces = (const int*)  d_in[1];   // [1,2048,3] i32
    const float* Km    = (const float*)d_in[2];   // [1,3,3]
    const float* Rm    = (const float*)d_in[3];   // [1,3,3]
    const float* tm    = (const float*)d_in[4];   // [1,3,1]
    float* out = (float*)d_out;

    {
        void* args[] = { (void*)&verts, (void*)&Km, (void*)&Rm, (void*)&tm };
        launch_pdl((void*)vert_kernel, dim3(N_V / 128), dim3(128), args);
    }
    {
        void* args[] = { (void*)&faces };
        launch_pdl((void*)face_kernel, dim3(M_F / 128), dim3(128), args);
    }
    {
        void* args[] = {};
        launch_pdl((void*)raster_kernel, dim3(TILES_X, TILES_Y, NSEG), dim3(NTHR), args);
    }
    {
        void* args[] = { (void*)&out };
        launch_pdl((void*)finalize_kernel, dim3((NPIX / 4 + 127) / 128), dim3(128), args);
    }
}